// round 11
// baseline (speedup 1.0000x reference)
#include <cuda_runtime.h>

// Problem constants
#define BB 8
#define CC 256
#define NN 65536            // 256*256 spatial
#define TILE 32             // pixels per tile
#define TILESPB 2048        // tiles per batch
#define BPB 76              // blocks per batch (batch-aligned)
#define TPB 27              // ceil(2048/76)
#define GRID_A (BB * BPB)   // 608 = 4 blocks/SM * 152 SMs
#define THREADS 128

// Output layout (flat float32 concat of reference returns)
#define OFF_LABELS  512
#define OFF_ONEHOT  (512 + BB * NN)              // 524800
#define OFF_CURDIST (OFF_ONEHOT + 2LL * BB * NN) // 1573376

// -------- device scratch (no allocations; zero-initialized) --------
__device__ float g_sums[BB * 2 * CC];   // [b][k][c] (re-zeroed by tail)
__device__ float g_counts[BB * 2];      // [b][k]
__device__ float g_centers[2 * CC];     // [k][c]
__device__ float g_cn[2 * CC];          // normalized, interleaved [c][k]
__device__ unsigned char g_labels[(long long)BB * NN];
__device__ float g_curdist;
__device__ int g_done;                  // reset by k_final
__device__ unsigned g_ticket;           // self-resetting

// -------- block reduce of 4 floats (128 threads / 4 warps) --------
__device__ __forceinline__ float4 blockReduce4(float4 v, float* scr) {
#pragma unroll
    for (int o = 16; o > 0; o >>= 1) {
        v.x += __shfl_down_sync(0xffffffffu, v.x, o);
        v.y += __shfl_down_sync(0xffffffffu, v.y, o);
        v.z += __shfl_down_sync(0xffffffffu, v.z, o);
        v.w += __shfl_down_sync(0xffffffffu, v.w, o);
    }
    int wid = threadIdx.x >> 5, lane = threadIdx.x & 31;
    __syncthreads();
    if (lane == 0) {
        scr[wid * 4 + 0] = v.x; scr[wid * 4 + 1] = v.y;
        scr[wid * 4 + 2] = v.z; scr[wid * 4 + 3] = v.w;
    }
    __syncthreads();
    if (threadIdx.x == 0) {
        float a = 0.f, b = 0.f, c = 0.f, d = 0.f;
#pragma unroll
        for (int w = 0; w < 4; w++) {
            a += scr[w * 4 + 0]; b += scr[w * 4 + 1];
            c += scr[w * 4 + 2]; d += scr[w * 4 + 3];
        }
        scr[0] = a; scr[1] = b; scr[2] = c; scr[3] = d;
    }
    __syncthreads();
    return make_float4(scr[0], scr[1], scr[2], scr[3]);
}

// ---- center-update tail for 128 threads: 2 channels per thread ----
__device__ __forceinline__ void update_tail(const float* __restrict__ cinit,
                                            int it, float* scr) {
    const int cA = threadIdx.x;       // channel A
    const int cB = threadIdx.x + 128; // channel B
    float coA0, coA1, coB0, coB1;
    if (it == 0) {
        coA0 = cinit[cA]; coA1 = cinit[CC + cA];
        coB0 = cinit[cB]; coB1 = cinit[CC + cB];
    } else {
        coA0 = g_centers[cA]; coA1 = g_centers[CC + cA];
        coB0 = g_centers[cB]; coB1 = g_centers[CC + cB];
    }
    float4 r = blockReduce4(make_float4(coA0 * coA0 + coB0 * coB0,
                                        coA1 * coA1 + coB1 * coB1, 0.f, 0.f), scr);
    float no0 = sqrtf(r.x), no1 = sqrtf(r.y);
    float ncA0 = 0.f, ncA1 = 0.f, ncB0 = 0.f, ncB1 = 0.f, cd = 0.f;
#pragma unroll
    for (int b = 0; b < BB; b++) {
        float cnt0 = g_counts[b * 2 + 0] + 1.0f;
        float cnt1 = g_counts[b * 2 + 1] + 1.0f;
        float ciA0 = g_sums[(b * 2 + 0) * CC + cA] / cnt0;
        float ciA1 = g_sums[(b * 2 + 1) * CC + cA] / cnt1;
        float ciB0 = g_sums[(b * 2 + 0) * CC + cB] / cnt0;
        float ciB1 = g_sums[(b * 2 + 1) * CC + cB] / cnt1;
        ncA0 += ciA0; ncA1 += ciA1; ncB0 += ciB0; ncB1 += ciB1;
        float4 q = blockReduce4(make_float4(
            ciA0 * coA0 + ciB0 * coB0, ciA0 * ciA0 + ciB0 * ciB0,
            ciA1 * coA1 + ciB1 * coB1, ciA1 * ciA1 + ciB1 * ciB1), scr);
        float den0 = fmaxf(sqrtf(q.y) * no0, 1e-8f);
        float den1 = fmaxf(sqrtf(q.w) * no1, 1e-8f);
        cd += 0.5f * (q.x / den0 + q.z / den1);
    }
    float cur = cd * 0.125f;
    ncA0 *= 0.125f; ncA1 *= 0.125f; ncB0 *= 0.125f; ncB1 *= 0.125f;
    float4 r2 = blockReduce4(make_float4(ncA0 * ncA0 + ncB0 * ncB0,
                                         ncA1 * ncA1 + ncB1 * ncB1, 0.f, 0.f), scr);
    float nn0 = fmaxf(sqrtf(r2.x), 1e-12f);
    float nn1 = fmaxf(sqrtf(r2.y), 1e-12f);
    g_centers[cA] = ncA0; g_centers[CC + cA] = ncA1;
    g_centers[cB] = ncB0; g_centers[CC + cB] = ncB1;
    g_cn[cA * 2 + 0] = ncA0 / nn0; g_cn[cA * 2 + 1] = ncA1 / nn1;
    g_cn[cB * 2 + 0] = ncB0 / nn0; g_cn[cB * 2 + 1] = ncB1 / nn1;
#pragma unroll
    for (int jj = 0; jj < 32; jj++) g_sums[jj * 128 + threadIdx.x] = 0.f;
    if (threadIdx.x < 16) g_counts[threadIdx.x] = 0.f;
    if (threadIdx.x == 0) {
        g_curdist = cur;
        if (cur < 0.01f) g_done = 1;
        g_ticket = 0u;
    }
}

// ======== assign: TT-64-style per-thread loop, 128-thread blocks ==========
__global__ void __launch_bounds__(THREADS, 4) k_assign(
        const float* __restrict__ F, const float* __restrict__ cinit, int it) {
    if (it > 0 && g_done) return;  // frozen after convergence
    __shared__ float s_part[64 * 17];   // [col = 8j+q][g], stride 17
    __shared__ float s_cn[2 * CC];      // interleaved [c][k]
    __shared__ float s_labs[TILE];
    __shared__ float scr[16];
    __shared__ int s_cnt;
    __shared__ unsigned s_rank;

    const int tid = threadIdx.x;
    if (it == 0) {
        // per-block redundant normalization of init centers (2 ch/thread)
        float cA0 = cinit[tid], cA1 = cinit[CC + tid];
        float cB0 = cinit[tid + 128], cB1 = cinit[CC + tid + 128];
        float4 r = blockReduce4(make_float4(cA0 * cA0 + cB0 * cB0,
                                            cA1 * cA1 + cB1 * cB1, 0.f, 0.f), scr);
        float n0 = fmaxf(sqrtf(r.x), 1e-12f);
        float n1 = fmaxf(sqrtf(r.y), 1e-12f);
        s_cn[tid * 2 + 0] = cA0 / n0; s_cn[tid * 2 + 1] = cA1 / n1;
        s_cn[(tid + 128) * 2 + 0] = cB0 / n0; s_cn[(tid + 128) * 2 + 1] = cB1 / n1;
    } else {
#pragma unroll
        for (int i = 0; i < 4; i++) s_cn[tid + 128 * i] = g_cn[tid + 128 * i];
    }
    if (tid == 0) s_cnt = 0;

    const int batch = blockIdx.x / BPB;
    const int bi = blockIdx.x % BPB;
    const int t0 = bi * TPB;
    int t1 = t0 + TPB; if (t1 > TILESPB) t1 = TILESPB;

    const int g = tid >> 3;      // channel group: channels c = g + 16k (g<16)
    const int j = tid & 7;       // pixel quad: pixels 4j..4j+3
    const float* Fb = F + (long long)batch * CC * NN + (long long)g * NN + 4 * j;
    const float2* cn2 = (const float2*)s_cn;

    float acc1[16], accT[16];
#pragma unroll
    for (int k = 0; k < 16; k++) { acc1[k] = 0.f; accT[k] = 0.f; }
    int accCnt = 0;
    __syncthreads();  // s_cn / s_cnt ready

    for (int t = t0; t < t1; t++) {
        const float* p = Fb + t * TILE;
        // ---- phase 1: streaming loads kept in registers; dots + totals ----
        float4 v[16];
        float dp[8];
#pragma unroll
        for (int q = 0; q < 8; q++) dp[q] = 0.f;
#pragma unroll
        for (int k = 0; k < 16; k++) {
            v[k] = __ldcs((const float4*)(p + (long long)k * (16 * NN)));
            float2 w = cn2[g + 16 * k];
            dp[0] = fmaf(v[k].x, w.x, dp[0]); dp[1] = fmaf(v[k].x, w.y, dp[1]);
            dp[2] = fmaf(v[k].y, w.x, dp[2]); dp[3] = fmaf(v[k].y, w.y, dp[3]);
            dp[4] = fmaf(v[k].z, w.x, dp[4]); dp[5] = fmaf(v[k].z, w.y, dp[5]);
            dp[6] = fmaf(v[k].w, w.x, dp[6]); dp[7] = fmaf(v[k].w, w.y, dp[7]);
            accT[k] += (v[k].x + v[k].y) + (v[k].z + v[k].w);
        }
        // harvest previous tile's count (race-free: before barrier)
        if (tid == 0) { accCnt += s_cnt; s_cnt = 0; }
        // store partials: [col][g], col = 8j+q (2-way write conflict, benign)
#pragma unroll
        for (int q = 0; q < 8; q++)
            s_part[(8 * j + q) * 17 + g] = dp[q];
        __syncthreads();

        // ---- phase 2: 64 threads reduce 16 groups -> labels ----
        if (tid < 64) {
            const int pp = tid >> 1, kk = tid & 1;
            const int col = 8 * (pp >> 2) + 2 * (pp & 3) + kk;
            float s = 0.f;
#pragma unroll
            for (int gg = 0; gg < 16; gg++) s += s_part[col * 17 + gg];
            float o = __shfl_xor_sync(0xffffffffu, s, 1);
            int lab = 0;
            if (!kk) {
                lab = (o > s) ? 1 : 0;  // argmin tie -> 0
                s_labs[pp] = (float)lab;
                g_labels[(long long)batch * NN + t * TILE + pp] = (unsigned char)lab;
            }
            unsigned bal = __ballot_sync(0xffffffffu, lab);
            if ((tid & 31) == 0) atomicAdd(&s_cnt, __popc(bal));
        }
        __syncthreads();

        // ---- phase 3: masked sums from REGISTERS ----
        float4 lb = *(const float4*)(s_labs + 4 * j);
#pragma unroll
        for (int k = 0; k < 16; k++) {
            float a = acc1[k];
            a = fmaf(lb.x, v[k].x, a); a = fmaf(lb.y, v[k].y, a);
            a = fmaf(lb.z, v[k].z, a); a = fmaf(lb.w, v[k].w, a);
            acc1[k] = a;
        }
    }
    __syncthreads();
    if (tid == 0) accCnt += s_cnt;

    // ---- flush: reduce across 8 j-lanes (contiguous in warp) + atomics ----
#pragma unroll
    for (int k = 0; k < 16; k++) {
        float a = acc1[k], s = accT[k];
#pragma unroll
        for (int o = 4; o > 0; o >>= 1) {
            a += __shfl_down_sync(0xffffffffu, a, o, 8);
            s += __shfl_down_sync(0xffffffffu, s, o, 8);
        }
        if (j == 0) {
            int c = g + 16 * k;
            atomicAdd(&g_sums[(batch * 2 + 1) * CC + c], a);
            atomicAdd(&g_sums[(batch * 2 + 0) * CC + c], s - a);
        }
    }
    if (tid == 0) {
        int npix = (t1 - t0) * TILE;
        atomicAdd(&g_counts[batch * 2 + 1], (float)accCnt);
        atomicAdd(&g_counts[batch * 2 + 0], (float)(npix - accCnt));
    }

    // ---- last-finishing block performs the center update in-kernel ----
    __threadfence();
    __syncthreads();
    if (tid == 0) s_rank = atomicAdd(&g_ticket, 1u);
    __syncthreads();
    if (s_rank != (unsigned)(GRID_A - 1)) return;
    __threadfence();  // acquire all blocks' atomics
    update_tail(cinit, it, scr);
}

// -------- finalize: write [centers | labels | onehot | cur_dist] --------
__global__ void k_final(float* __restrict__ out, long long outSize) {
    long long i = (long long)blockIdx.x * 256 + threadIdx.x;
    if (i < 512 && i < outSize) out[i] = g_centers[i];
    if (i < (long long)BB * NN) {
        float lab = (float)g_labels[i];
        long long o1 = OFF_LABELS + i;
        long long o2 = OFF_ONEHOT + 2 * i;
        if (o1 < outSize) out[o1] = lab;
        if (o2 + 1 < outSize)
            *(float2*)(out + o2) = make_float2(1.0f - lab, lab);
    }
    if (i == 0) {
        if (OFF_CURDIST < outSize) out[OFF_CURDIST] = g_curdist;
        g_done = 0;   // reset for next graph replay
    }
}

extern "C" void kernel_launch(void* const* d_in, const int* in_sizes, int n_in,
                              void* d_out, int out_size) {
    const float* F = (const float*)d_in[0];
    const float* cinit = (const float*)d_in[1];
    if (n_in >= 2 && in_sizes[0] == 2 * CC) {  // tolerate swapped metadata order
        F = (const float*)d_in[1];
        cinit = (const float*)d_in[0];
    }
    for (int it = 0; it < 3; it++) {
        k_assign<<<GRID_A, THREADS>>>(F, cinit, it);
    }
    k_final<<<(BB * NN) / 256, 256>>>((float*)d_out, (long long)out_size);
}